// round 1
// baseline (speedup 1.0000x reference)
#include <cuda_runtime.h>
#include <math.h>
#include <stdint.h>

// ---------------- problem constants ----------------
#define T_  4
#define B_  16
#define C_  512
#define H_  16
#define W_  16
#define N_  256            // H*W tokens per image
#define NH_ 8
#define D_  64             // head dim
#define M_  (T_*B_*N_)     // 16384 rows
#define HID_ 2048
#define IMG_ (B_*C_*H_*W_) // per-timestep image elements = 2097152
#define ROWS_PER_T (B_*N_) // 4096

// ---------------- scratch (static device arrays; no allocation) -------------
__device__ float g_s  [T_*IMG_];        // spikes of input LIF   [T,B,C,H,W]
__device__ float g_xt [M_*C_];          // token stream          [T*B*N, C]
__device__ float g_h  [M_*C_];          // LN+LIF spikes
__device__ float g_qkv[M_*3*C_];        // qkv, then spiked qkv in-place
__device__ float g_a  [M_*C_];          // attention out, then spiked in-place
__device__ float g_xt2[M_*C_];          // after proj residual
__device__ float g_mlp[M_*HID_];        // fc1 out, then spiked in-place

__device__ __forceinline__ float sigm(float w){ return 1.0f/(1.0f+expf(-w)); }

// ---------------- K1: LIF over input x -> g_s ----------------
__global__ void k_lif_x(const float* __restrict__ x, const float* __restrict__ lifw){
    int e = blockIdx.x*blockDim.x + threadIdx.x;
    if (e >= IMG_) return;
    float decay = sigm(lifw[0]);
    float v = 0.f;
    #pragma unroll
    for (int t=0;t<T_;t++){
        float xv = x[(size_t)t*IMG_ + e];
        v += (xv - v)*decay;
        float sp = (v >= 1.0f) ? 1.f : 0.f;
        g_s[(size_t)t*IMG_ + e] = sp;
        if (sp > 0.f) v = 0.f;
    }
}

// ---------------- K2: depthwise 3x3 conv + bias + residual, write tokens ----
__global__ void k_conv(const float* __restrict__ x,
                       const float* __restrict__ cw,
                       const float* __restrict__ cb){
    int idx = blockIdx.x*blockDim.x + threadIdx.x;   // over T*B*C*H*W = 8388608
    if (idx >= T_*IMG_) return;
    int w  = idx & (W_-1);
    int h  = (idx >> 4) & (H_-1);
    int c  = (idx >> 8) & (C_-1);
    int tb = idx >> 17;                               // t*B + b
    const float* sp = g_s + ((size_t)tb*C_ + c)*(H_*W_);
    float acc = cb[c];
    const float* wk = cw + c*9;
    #pragma unroll
    for (int kh=0;kh<3;kh++){
        int hh = h + kh - 1;
        if (hh < 0 || hh >= H_) continue;
        #pragma unroll
        for (int kw=0;kw<3;kw++){
            int ww = w + kw - 1;
            if (ww < 0 || ww >= W_) continue;
            acc += sp[hh*W_ + ww] * wk[kh*3 + kw];
        }
    }
    float val = x[idx] + acc;
    int n = h*W_ + w;
    g_xt[((size_t)tb*N_ + n)*C_ + c] = val;
}

// ---------------- K3: LayerNorm over C + LIF over T (fused) -----------------
__global__ void k_ln_lif(const float* __restrict__ in, float* __restrict__ out,
                         const float* __restrict__ gam, const float* __restrict__ bet,
                         const float* __restrict__ lifw, int lidx){
    int bn = blockIdx.x;           // 0..4095 (b*N + n)
    int c  = threadIdx.x;          // 512 threads, one per channel
    float decay = sigm(lifw[lidx]);
    float gg = gam[c], bb = bet[c];
    __shared__ float sh1[16], sh2[16];
    int lane = c & 31, wid = c >> 5;
    float v = 0.f;
    for (int t=0;t<T_;t++){
        float xv = in[((size_t)(t*ROWS_PER_T + bn))*C_ + c];
        float a1 = xv, a2 = xv*xv;
        #pragma unroll
        for (int o=16;o>0;o>>=1){
            a1 += __shfl_down_sync(0xffffffffu, a1, o);
            a2 += __shfl_down_sync(0xffffffffu, a2, o);
        }
        if (lane==0){ sh1[wid]=a1; sh2[wid]=a2; }
        __syncthreads();
        if (wid==0){
            float b1 = (lane<16)? sh1[lane] : 0.f;
            float b2 = (lane<16)? sh2[lane] : 0.f;
            #pragma unroll
            for (int o=8;o>0;o>>=1){
                b1 += __shfl_down_sync(0xffffffffu, b1, o);
                b2 += __shfl_down_sync(0xffffffffu, b2, o);
            }
            if (lane==0){ sh1[0]=b1; sh2[0]=b2; }
        }
        __syncthreads();
        float mean = sh1[0]*(1.0f/C_);
        float var  = sh2[0]*(1.0f/C_) - mean*mean;
        float ln = (xv - mean)*rsqrtf(var + 1e-5f)*gg + bb;
        v += (ln - v)*decay;
        float sp = (v >= 1.0f) ? 1.f : 0.f;
        out[((size_t)(t*ROWS_PER_T + bn))*C_ + c] = sp;
        if (sp > 0.f) v = 0.f;
        __syncthreads();
    }
}

// ---------------- K4: SGEMM  out[M,N] = A[M,K] @ W[N,K]^T (+bias)(+res) -----
// 64x64 tile, BK=16, 256 threads, 4x4 per thread.
__global__ void k_gemm(const float* __restrict__ A, const float* __restrict__ Wt,
                       const float* __restrict__ bias, const float* __restrict__ res,
                       float* __restrict__ out, int Ndim, int K){
    __shared__ float As[16][68];
    __shared__ float Ws[16][68];
    int bm = blockIdx.y * 64;
    int bn = blockIdx.x * 64;
    int tid = threadIdx.x;
    int tm = tid >> 4, tn = tid & 15;
    float acc[4][4] = {};
    int lm = tid >> 2;           // 0..63
    int lk = (tid & 3) * 4;      // 0,4,8,12
    for (int k0=0; k0<K; k0+=16){
        float4 av = *(const float4*)&A [(size_t)(bm+lm)*K + k0 + lk];
        float4 wv = *(const float4*)&Wt[(size_t)(bn+lm)*K + k0 + lk];
        As[lk+0][lm]=av.x; As[lk+1][lm]=av.y; As[lk+2][lm]=av.z; As[lk+3][lm]=av.w;
        Ws[lk+0][lm]=wv.x; Ws[lk+1][lm]=wv.y; Ws[lk+2][lm]=wv.z; Ws[lk+3][lm]=wv.w;
        __syncthreads();
        #pragma unroll
        for (int kk=0;kk<16;kk++){
            float4 ra = *(const float4*)&As[kk][tm*4];
            float4 rb = *(const float4*)&Ws[kk][tn*4];
            float raa[4] = {ra.x,ra.y,ra.z,ra.w};
            float rbb[4] = {rb.x,rb.y,rb.z,rb.w};
            #pragma unroll
            for (int i=0;i<4;i++)
                #pragma unroll
                for (int j=0;j<4;j++)
                    acc[i][j] += raa[i]*rbb[j];
        }
        __syncthreads();
    }
    #pragma unroll
    for (int i=0;i<4;i++){
        int m = bm + tm*4 + i;
        #pragma unroll
        for (int j=0;j<4;j++){
            int n = bn + tn*4 + j;
            float v = acc[i][j];
            if (bias) v += bias[n];
            if (res)  v += res[(size_t)m*Ndim + n];
            out[(size_t)m*Ndim + n] = v;
        }
    }
}

// ---------------- K5a: LIF over T for qkv (3 decays by channel slice) -------
__global__ void k_lif_qkv(const float* __restrict__ lifw){
    size_t e = (size_t)blockIdx.x*blockDim.x + threadIdx.x;  // over 4096*1536
    const size_t inner = (size_t)ROWS_PER_T * 3*C_;
    if (e >= inner) return;
    int cc = (int)(e % (3*C_));
    float decay = sigm(lifw[2 + cc/C_]);
    float v = 0.f;
    #pragma unroll
    for (int t=0;t<T_;t++){
        float xv = g_qkv[(size_t)t*inner + e];
        v += (xv - v)*decay;
        float sp = (v >= 1.0f) ? 1.f : 0.f;
        g_qkv[(size_t)t*inner + e] = sp;
        if (sp > 0.f) v = 0.f;
    }
}

// ---------------- K5b: generic in-place LIF over T --------------------------
__global__ void k_lif_seq(float* __restrict__ buf, size_t tstride,
                          const float* __restrict__ lifw, int lidx){
    size_t e = (size_t)blockIdx.x*blockDim.x + threadIdx.x;
    if (e >= tstride) return;
    float decay = sigm(lifw[lidx]);
    float v = 0.f;
    #pragma unroll
    for (int t=0;t<T_;t++){
        float xv = buf[(size_t)t*tstride + e];
        v += (xv - v)*decay;
        float sp = (v >= 1.0f) ? 1.f : 0.f;
        buf[(size_t)t*tstride + e] = sp;
        if (sp > 0.f) v = 0.f;
    }
}

// ---------------- K6: linear attention per (t,b,h) --------------------------
// kv = k^T v (64x64), a = q @ kv * scale
__global__ void k_attn(){
    int blk = blockIdx.x;            // 0..511
    int h  = blk & (NH_-1);
    int tb = blk >> 3;               // t*B + b
    __shared__ float kv[64*64];
    __shared__ float ks[64*64];
    __shared__ float vs[64*64];
    const float* base = g_qkv + (size_t)tb*N_*(3*C_);
    int tid = threadIdx.x;           // 256 threads
    int ti = tid >> 4, tj = tid & 15;
    float acc[4][4] = {};
    for (int n0=0; n0<N_; n0+=64){
        #pragma unroll
        for (int r=0;r<16;r++){
            int l = tid + r*256;
            int nn = l >> 6, i = l & 63;
            size_t gi = (size_t)(n0+nn)*(3*C_) + h*D_ + i;
            ks[l] = base[gi + C_];
            vs[l] = base[gi + 2*C_];
        }
        __syncthreads();
        #pragma unroll 8
        for (int nn=0; nn<64; nn++){
            float ra[4], rb[4];
            #pragma unroll
            for (int i=0;i<4;i++) ra[i] = ks[nn*64 + ti*4 + i];
            #pragma unroll
            for (int j=0;j<4;j++) rb[j] = vs[nn*64 + tj*4 + j];
            #pragma unroll
            for (int i=0;i<4;i++)
                #pragma unroll
                for (int j=0;j<4;j++)
                    acc[i][j] += ra[i]*rb[j];
        }
        __syncthreads();
    }
    #pragma unroll
    for (int i=0;i<4;i++)
        #pragma unroll
        for (int j=0;j<4;j++)
            kv[(ti*4+i)*64 + tj*4+j] = acc[i][j];
    __syncthreads();

    // phase 2: thread = token row n = tid
    float q[64];
    #pragma unroll
    for (int i=0;i<64;i++) q[i] = base[(size_t)tid*(3*C_) + h*D_ + i];
    const float scale = 0.125f;      // 64^-0.5
    float* aout = g_a + ((size_t)tb*N_ + tid)*C_ + h*D_;
    #pragma unroll 4
    for (int j=0;j<64;j++){
        float s = 0.f;
        #pragma unroll
        for (int i=0;i<64;i++) s += q[i]*kv[i*64 + j];
        aout[j] = s*scale;
    }
}

// ---------------- K7: tokens [tb, N, C] -> output [tb, C, N] ----------------
__global__ void k_tr_out(float* __restrict__ out){
    __shared__ float tile[32][33];
    int tb = blockIdx.z;
    int n0 = blockIdx.y*32, c0 = blockIdx.x*32;
    const float* src = g_xt + (size_t)tb*N_*C_;
    float* dst = out + (size_t)tb*C_*N_;
    int tx = threadIdx.x, ty = threadIdx.y;    // 32 x 8
    #pragma unroll
    for (int r=0;r<32;r+=8)
        tile[ty+r][tx] = src[(size_t)(n0+ty+r)*C_ + c0+tx];
    __syncthreads();
    #pragma unroll
    for (int r=0;r<32;r+=8)
        dst[(size_t)(c0+ty+r)*N_ + n0+tx] = tile[tx][ty+r];
}

// ---------------- host-side orchestration -----------------------------------
extern "C" void kernel_launch(void* const* d_in, const int* in_sizes, int n_in,
                              void* d_out, int out_size){
    const float* x      = (const float*)d_in[0];
    const float* conv_w = (const float*)d_in[1];
    const float* conv_b = (const float*)d_in[2];
    const float* ln1_g  = (const float*)d_in[3];
    const float* ln1_b  = (const float*)d_in[4];
    const float* qkv_w  = (const float*)d_in[5];
    const float* proj_w = (const float*)d_in[6];
    const float* proj_b = (const float*)d_in[7];
    const float* ln2_g  = (const float*)d_in[8];
    const float* ln2_b  = (const float*)d_in[9];
    const float* fc1_w  = (const float*)d_in[10];
    const float* fc1_b  = (const float*)d_in[11];
    const float* fc2_w  = (const float*)d_in[12];
    const float* fc2_b  = (const float*)d_in[13];
    const float* lif_w  = (const float*)d_in[14];
    float* out = (float*)d_out;

    float *p_xt, *p_h, *p_qkv, *p_a, *p_xt2, *p_mlp;
    cudaGetSymbolAddress((void**)&p_xt,  g_xt);
    cudaGetSymbolAddress((void**)&p_h,   g_h);
    cudaGetSymbolAddress((void**)&p_qkv, g_qkv);
    cudaGetSymbolAddress((void**)&p_a,   g_a);
    cudaGetSymbolAddress((void**)&p_xt2, g_xt2);
    cudaGetSymbolAddress((void**)&p_mlp, g_mlp);

    // 1. input LIF
    k_lif_x<<<(IMG_+255)/256, 256>>>(x, lif_w);
    // 2. depthwise conv + residual -> tokens g_xt
    k_conv<<<(T_*IMG_+255)/256, 256>>>(x, conv_w, conv_b);
    // 3. LN1 + LIF -> g_h
    k_ln_lif<<<ROWS_PER_T, C_>>>(p_xt, p_h, ln1_g, ln1_b, lif_w, 1);
    // 4. qkv GEMM: [16384,512] @ [1536,512]^T -> g_qkv
    k_gemm<<<dim3((3*C_)/64, M_/64), 256>>>(p_h, qkv_w, nullptr, nullptr, p_qkv, 3*C_, C_);
    // 5. LIF on q,k,v (in place)
    {
        size_t inner = (size_t)ROWS_PER_T*3*C_;
        k_lif_qkv<<<(unsigned)((inner+255)/256), 256>>>(lif_w);
    }
    // 6. attention -> g_a
    k_attn<<<T_*B_*NH_, 256>>>();
    // 7. LIF on a (in place)
    k_lif_seq<<<(ROWS_PER_T*C_+255)/256, 256>>>(p_a, (size_t)ROWS_PER_T*C_, lif_w, 5);
    // 8. proj GEMM + bias + residual(g_xt) -> g_xt2
    k_gemm<<<dim3(C_/64, M_/64), 256>>>(p_a, proj_w, proj_b, p_xt, p_xt2, C_, C_);
    // 9. LN2 + LIF -> g_h
    k_ln_lif<<<ROWS_PER_T, C_>>>(p_xt2, p_h, ln2_g, ln2_b, lif_w, 6);
    // 10. fc1 GEMM + bias -> g_mlp
    k_gemm<<<dim3(HID_/64, M_/64), 256>>>(p_h, fc1_w, fc1_b, nullptr, p_mlp, HID_, C_);
    // 11. LIF on mlp (in place)
    k_lif_seq<<<(ROWS_PER_T*HID_+255)/256, 256>>>(p_mlp, (size_t)ROWS_PER_T*HID_, lif_w, 7);
    // 12. fc2 GEMM + bias + residual(g_xt2) -> g_xt (reuse)
    k_gemm<<<dim3(C_/64, M_/64), 256>>>(p_mlp, fc2_w, fc2_b, p_xt2, p_xt, C_, HID_);
    // 13. transpose tokens back to [T,B,C,H,W]
    k_tr_out<<<dim3(C_/32, N_/32, T_*B_), dim3(32,8)>>>(out);
}

// round 3
// speedup vs baseline: 4.0023x; 4.0023x over previous
#include <cuda_runtime.h>
#include <cuda_fp16.h>
#include <math.h>
#include <stdint.h>

// ---------------- problem constants ----------------
#define T_  4
#define B_  16
#define C_  512
#define H_  16
#define W_  16
#define N_  256
#define NH_ 8
#define D_  64
#define M_  (T_*B_*N_)     // 16384
#define HID_ 2048
#define IMG_ (B_*C_*H_*W_) // 2097152
#define ROWS_PER_T (B_*N_) // 4096

// ---------------- scratch ----------------
__device__ float g_s  [T_*IMG_];
__device__ float g_xt [M_*C_];
__device__ float g_qkv[M_*3*C_];
__device__ float g_a  [M_*C_];
__device__ float g_xt2[M_*C_];
__device__ float g_mlp[M_*HID_];
__device__ __half g_h16[M_*C_];     // LN spikes (fp16, exact 0/1)
__device__ __half g_a16[M_*C_];     // attention spikes fp16
__device__ __half g_m16[M_*HID_];   // mlp spikes fp16
__device__ __half g_w16[HID_*C_];   // current weight fp16

__device__ __forceinline__ float sigm(float w){ return 1.0f/(1.0f+expf(-w)); }

__device__ __forceinline__ uint32_t s2u(const void* p){
    uint32_t a;
    asm("{ .reg .u64 t; cvta.to.shared.u64 t, %1; cvt.u32.u64 %0, t; }" : "=r"(a) : "l"(p));
    return a;
}
__device__ __forceinline__ void cp16(uint32_t s, const void* g){
    asm volatile("cp.async.cg.shared.global [%0], [%1], 16;" :: "r"(s), "l"(g));
}
__device__ __forceinline__ void ldsm4(uint32_t* r, uint32_t addr){
    asm volatile("ldmatrix.sync.aligned.m8n8.x4.shared.b16 {%0,%1,%2,%3}, [%4];"
                 : "=r"(r[0]), "=r"(r[1]), "=r"(r[2]), "=r"(r[3]) : "r"(addr));
}
__device__ __forceinline__ void mma16816(float* c, const uint32_t* a, uint32_t b0, uint32_t b1){
    asm volatile(
        "mma.sync.aligned.m16n8k16.row.col.f32.f16.f16.f32 "
        "{%0,%1,%2,%3}, {%4,%5,%6,%7}, {%8,%9}, {%0,%1,%2,%3};"
        : "+f"(c[0]), "+f"(c[1]), "+f"(c[2]), "+f"(c[3])
        : "r"(a[0]), "r"(a[1]), "r"(a[2]), "r"(a[3]), "r"(b0), "r"(b1));
}

// ---------------- HMMA GEMM: out[M,N] = A[M,K](f16) @ W[N,K]^T(f16) ---------
// 128x128 CTA tile, 8 warps (2m x 4n), warp tile 64x32, BK=32, double buffer.
#define LDT 40   // 32 + 8 pad halves per smem row (80B stride, conflict-free)

__global__ void __launch_bounds__(256) tc_gemm(
        const __half* __restrict__ A, const __half* __restrict__ Wt,
        const float* __restrict__ bias, const float* __restrict__ res,
        float* __restrict__ out, int Ndim, int K){
    __shared__ __half sA[2][128*LDT];
    __shared__ __half sB[2][128*LDT];
    int tid = threadIdx.x;
    int warp = tid >> 5, lane = tid & 31;
    int wm = (warp & 1) * 64;
    int wn = (warp >> 1) * 32;
    int bm = blockIdx.y * 128, bn = blockIdx.x * 128;
    float acc[4][4][4] = {};

    int l8 = lane >> 3;
    int arow = (lane & 7) + (l8 & 1) * 8;
    int acol = (l8 >> 1) * 8;
    int brow = (lane & 7) + (l8 >> 1) * 8;
    int bcol = (l8 & 1) * 8;

    const int NC = K / 32;
    // prologue
    {
        #pragma unroll
        for (int it = 0; it < 2; it++){
            int task = tid + it*256;
            int row = task >> 2, ch = task & 3;
            cp16(s2u(&sA[0][row*LDT + ch*8]), A  + (size_t)(bm+row)*K + ch*8);
            cp16(s2u(&sB[0][row*LDT + ch*8]), Wt + (size_t)(bn+row)*K + ch*8);
        }
        asm volatile("cp.async.commit_group;");
    }

    for (int c = 0; c < NC; c++){
        int buf = c & 1;
        asm volatile("cp.async.wait_group 0;" ::: "memory");
        __syncthreads();
        if (c + 1 < NC){
            int nb = buf ^ 1, k0 = (c+1)*32;
            #pragma unroll
            for (int it = 0; it < 2; it++){
                int task = tid + it*256;
                int row = task >> 2, ch = task & 3;
                cp16(s2u(&sA[nb][row*LDT + ch*8]), A  + (size_t)(bm+row)*K + k0 + ch*8);
                cp16(s2u(&sB[nb][row*LDT + ch*8]), Wt + (size_t)(bn+row)*K + k0 + ch*8);
            }
            asm volatile("cp.async.commit_group;");
        }
        #pragma unroll
        for (int ks = 0; ks < 2; ks++){
            uint32_t af[4][4], bf[2][4];
            #pragma unroll
            for (int mi = 0; mi < 4; mi++)
                ldsm4(af[mi], s2u(&sA[buf][(wm + mi*16 + arow)*LDT + ks*16 + acol]));
            #pragma unroll
            for (int np = 0; np < 2; np++)
                ldsm4(bf[np], s2u(&sB[buf][(wn + np*16 + brow)*LDT + ks*16 + bcol]));
            #pragma unroll
            for (int mi = 0; mi < 4; mi++)
                #pragma unroll
                for (int ni = 0; ni < 4; ni++)
                    mma16816(acc[mi][ni], af[mi],
                             bf[ni>>1][2*(ni&1)], bf[ni>>1][2*(ni&1)+1]);
        }
        __syncthreads();
    }

    // epilogue: lane g=lane/4 rows {g, g+8}, i=lane%4 cols {2i, 2i+1}
    int g = lane >> 2, i2 = (lane & 3) * 2;
    #pragma unroll
    for (int mi = 0; mi < 4; mi++){
        int r0 = bm + wm + mi*16 + g;
        #pragma unroll
        for (int ni = 0; ni < 4; ni++){
            int col = bn + wn + ni*8 + i2;
            float b0 = bias ? bias[col]   : 0.f;
            float b1 = bias ? bias[col+1] : 0.f;
            float v00 = acc[mi][ni][0] + b0, v01 = acc[mi][ni][1] + b1;
            float v10 = acc[mi][ni][2] + b0, v11 = acc[mi][ni][3] + b1;
            size_t o0 = (size_t)r0*Ndim + col;
            size_t o1 = (size_t)(r0+8)*Ndim + col;
            if (res){
                v00 += res[o0]; v01 += res[o0+1];
                v10 += res[o1]; v11 += res[o1+1];
            }
            *(float2*)&out[o0] = make_float2(v00, v01);
            *(float2*)&out[o1] = make_float2(v10, v11);
        }
    }
}

// ---------------- f32 -> f16 convert ----------------
__global__ void k_f2h(const float* __restrict__ in, __half* __restrict__ out, int n){
    int i = blockIdx.x*blockDim.x + threadIdx.x;
    if (i < n) out[i] = __float2half_rn(in[i]);
}

// ---------------- K1: LIF over input x -> g_s ----------------
__global__ void k_lif_x(const float* __restrict__ x, const float* __restrict__ lifw){
    int e = blockIdx.x*blockDim.x + threadIdx.x;
    if (e >= IMG_) return;
    float decay = sigm(lifw[0]);
    float v = 0.f;
    #pragma unroll
    for (int t=0;t<T_;t++){
        float xv = x[(size_t)t*IMG_ + e];
        v += (xv - v)*decay;
        float sp = (v >= 1.0f) ? 1.f : 0.f;
        g_s[(size_t)t*IMG_ + e] = sp;
        if (sp > 0.f) v = 0.f;
    }
}

// ---------------- K2: depthwise conv + residual -> tokens -------------------
__global__ void k_conv(const float* __restrict__ x,
                       const float* __restrict__ cw,
                       const float* __restrict__ cb){
    int idx = blockIdx.x*blockDim.x + threadIdx.x;
    if (idx >= T_*IMG_) return;
    int w  = idx & (W_-1);
    int h  = (idx >> 4) & (H_-1);
    int c  = (idx >> 8) & (C_-1);
    int tb = idx >> 17;
    const float* sp = g_s + ((size_t)tb*C_ + c)*(H_*W_);
    float acc = cb[c];
    const float* wk = cw + c*9;
    #pragma unroll
    for (int kh=0;kh<3;kh++){
        int hh = h + kh - 1;
        if (hh < 0 || hh >= H_) continue;
        #pragma unroll
        for (int kw=0;kw<3;kw++){
            int ww = w + kw - 1;
            if (ww < 0 || ww >= W_) continue;
            acc += sp[hh*W_ + ww] * wk[kh*3 + kw];
        }
    }
    float val = x[idx] + acc;
    int n = h*W_ + w;
    g_xt[((size_t)tb*N_ + n)*C_ + c] = val;
}

// ---------------- K3: LayerNorm + LIF -> fp16 spikes ------------------------
__global__ void k_ln_lif(const float* __restrict__ in, __half* __restrict__ out,
                         const float* __restrict__ gam, const float* __restrict__ bet,
                         const float* __restrict__ lifw, int lidx){
    int bn = blockIdx.x;
    int c  = threadIdx.x;
    float decay = sigm(lifw[lidx]);
    float gg = gam[c], bb = bet[c];
    __shared__ float sh1[16], sh2[16];
    int lane = c & 31, wid = c >> 5;
    float v = 0.f;
    for (int t=0;t<T_;t++){
        float xv = in[((size_t)(t*ROWS_PER_T + bn))*C_ + c];
        float a1 = xv, a2 = xv*xv;
        #pragma unroll
        for (int o=16;o>0;o>>=1){
            a1 += __shfl_down_sync(0xffffffffu, a1, o);
            a2 += __shfl_down_sync(0xffffffffu, a2, o);
        }
        if (lane==0){ sh1[wid]=a1; sh2[wid]=a2; }
        __syncthreads();
        if (wid==0){
            float b1 = (lane<16)? sh1[lane] : 0.f;
            float b2 = (lane<16)? sh2[lane] : 0.f;
            #pragma unroll
            for (int o=8;o>0;o>>=1){
                b1 += __shfl_down_sync(0xffffffffu, b1, o);
                b2 += __shfl_down_sync(0xffffffffu, b2, o);
            }
            if (lane==0){ sh1[0]=b1; sh2[0]=b2; }
        }
        __syncthreads();
        float mean = sh1[0]*(1.0f/C_);
        float var  = sh2[0]*(1.0f/C_) - mean*mean;
        float ln = (xv - mean)*rsqrtf(var + 1e-5f)*gg + bb;
        v += (ln - v)*decay;
        float sp = (v >= 1.0f) ? 1.f : 0.f;
        out[((size_t)(t*ROWS_PER_T + bn))*C_ + c] = __float2half_rn(sp);
        if (sp > 0.f) v = 0.f;
        __syncthreads();
    }
}

// ---------------- K5a: LIF for qkv (in-place fp32, for attention) -----------
__global__ void k_lif_qkv(const float* __restrict__ lifw){
    size_t e = (size_t)blockIdx.x*blockDim.x + threadIdx.x;
    const size_t inner = (size_t)ROWS_PER_T * 3*C_;
    if (e >= inner) return;
    int cc = (int)(e % (3*C_));
    float decay = sigm(lifw[2 + cc/C_]);
    float v = 0.f;
    #pragma unroll
    for (int t=0;t<T_;t++){
        float xv = g_qkv[(size_t)t*inner + e];
        v += (xv - v)*decay;
        float sp = (v >= 1.0f) ? 1.f : 0.f;
        g_qkv[(size_t)t*inner + e] = sp;
        if (sp > 0.f) v = 0.f;
    }
}

// ---------------- K5b: LIF fp32 in -> fp16 spikes out -----------------------
__global__ void k_lif_seq_h(const float* __restrict__ in, __half* __restrict__ out,
                            size_t tstride, const float* __restrict__ lifw, int lidx){
    size_t e = (size_t)blockIdx.x*blockDim.x + threadIdx.x;
    if (e >= tstride) return;
    float decay = sigm(lifw[lidx]);
    float v = 0.f;
    #pragma unroll
    for (int t=0;t<T_;t++){
        float xv = in[(size_t)t*tstride + e];
        v += (xv - v)*decay;
        float sp = (v >= 1.0f) ? 1.f : 0.f;
        out[(size_t)t*tstride + e] = __float2half_rn(sp);
        if (sp > 0.f) v = 0.f;
    }
}

// ---------------- K6: linear attention per (t,b,h) --------------------------
__global__ void k_attn(){
    int blk = blockIdx.x;
    int h  = blk & (NH_-1);
    int tb = blk >> 3;
    __shared__ float kv[64*64];
    __shared__ float ks[64*64];
    __shared__ float vs[64*64];
    const float* base = g_qkv + (size_t)tb*N_*(3*C_);
    int tid = threadIdx.x;
    int ti = tid >> 4, tj = tid & 15;
    float acc[4][4] = {};
    for (int n0=0; n0<N_; n0+=64){
        #pragma unroll
        for (int r=0;r<16;r++){
            int l = tid + r*256;
            int nn = l >> 6, i = l & 63;
            size_t gi = (size_t)(n0+nn)*(3*C_) + h*D_ + i;
            ks[l] = base[gi + C_];
            vs[l] = base[gi + 2*C_];
        }
        __syncthreads();
        #pragma unroll 8
        for (int nn=0; nn<64; nn++){
            float ra[4], rb[4];
            #pragma unroll
            for (int i=0;i<4;i++) ra[i] = ks[nn*64 + ti*4 + i];
            #pragma unroll
            for (int j=0;j<4;j++) rb[j] = vs[nn*64 + tj*4 + j];
            #pragma unroll
            for (int i=0;i<4;i++)
                #pragma unroll
                for (int j=0;j<4;j++)
                    acc[i][j] += ra[i]*rb[j];
        }
        __syncthreads();
    }
    #pragma unroll
    for (int i=0;i<4;i++)
        #pragma unroll
        for (int j=0;j<4;j++)
            kv[(ti*4+i)*64 + tj*4+j] = acc[i][j];
    __syncthreads();

    float q[64];
    #pragma unroll
    for (int i=0;i<64;i++) q[i] = base[(size_t)tid*(3*C_) + h*D_ + i];
    const float scale = 0.125f;
    float* aout = g_a + ((size_t)tb*N_ + tid)*C_ + h*D_;
    #pragma unroll 4
    for (int j=0;j<64;j++){
        float s = 0.f;
        #pragma unroll
        for (int i=0;i<64;i++) s += q[i]*kv[i*64 + j];
        aout[j] = s*scale;
    }
}

// ---------------- K7: tokens -> output layout -------------------------------
__global__ void k_tr_out(float* __restrict__ out){
    __shared__ float tile[32][33];
    int tb = blockIdx.z;
    int n0 = blockIdx.y*32, c0 = blockIdx.x*32;
    const float* src = g_xt + (size_t)tb*N_*C_;
    float* dst = out + (size_t)tb*C_*N_;
    int tx = threadIdx.x, ty = threadIdx.y;
    #pragma unroll
    for (int r=0;r<32;r+=8)
        tile[ty+r][tx] = src[(size_t)(n0+ty+r)*C_ + c0+tx];
    __syncthreads();
    #pragma unroll
    for (int r=0;r<32;r+=8)
        dst[(size_t)(c0+ty+r)*N_ + n0+tx] = tile[tx][ty+r];
}

// ---------------- host orchestration ----------------------------------------
extern "C" void kernel_launch(void* const* d_in, const int* in_sizes, int n_in,
                              void* d_out, int out_size){
    const float* x      = (const float*)d_in[0];
    const float* conv_w = (const float*)d_in[1];
    const float* conv_b = (const float*)d_in[2];
    const float* ln1_g  = (const float*)d_in[3];
    const float* ln1_b  = (const float*)d_in[4];
    const float* qkv_w  = (const float*)d_in[5];
    const float* proj_w = (const float*)d_in[6];
    const float* proj_b = (const float*)d_in[7];
    const float* ln2_g  = (const float*)d_in[8];
    const float* ln2_b  = (const float*)d_in[9];
    const float* fc1_w  = (const float*)d_in[10];
    const float* fc1_b  = (const float*)d_in[11];
    const float* fc2_w  = (const float*)d_in[12];
    const float* fc2_b  = (const float*)d_in[13];
    const float* lif_w  = (const float*)d_in[14];
    float* out = (float*)d_out;

    float *p_xt, *p_qkv, *p_a, *p_xt2, *p_mlp;
    __half *p_h16, *p_a16, *p_m16, *p_w16;
    cudaGetSymbolAddress((void**)&p_xt,  g_xt);
    cudaGetSymbolAddress((void**)&p_qkv, g_qkv);
    cudaGetSymbolAddress((void**)&p_a,   g_a);
    cudaGetSymbolAddress((void**)&p_xt2, g_xt2);
    cudaGetSymbolAddress((void**)&p_mlp, g_mlp);
    cudaGetSymbolAddress((void**)&p_h16, g_h16);
    cudaGetSymbolAddress((void**)&p_a16, g_a16);
    cudaGetSymbolAddress((void**)&p_m16, g_m16);
    cudaGetSymbolAddress((void**)&p_w16, g_w16);

    k_lif_x<<<(IMG_+255)/256, 256>>>(x, lif_w);
    k_conv<<<(T_*IMG_+255)/256, 256>>>(x, conv_w, conv_b);
    k_ln_lif<<<ROWS_PER_T, C_>>>(p_xt, p_h16, ln1_g, ln1_b, lif_w, 1);

    k_f2h<<<(3*C_*C_+255)/256, 256>>>(qkv_w, p_w16, 3*C_*C_);
    tc_gemm<<<dim3((3*C_)/128, M_/128), 256>>>(p_h16, p_w16, nullptr, nullptr, p_qkv, 3*C_, C_);

    {
        size_t inner = (size_t)ROWS_PER_T*3*C_;
        k_lif_qkv<<<(unsigned)((inner+255)/256), 256>>>(lif_w);
    }
    k_attn<<<T_*B_*NH_, 256>>>();
    k_lif_seq_h<<<(ROWS_PER_T*C_+255)/256, 256>>>(p_a, p_a16, (size_t)ROWS_PER_T*C_, lif_w, 5);

    k_f2h<<<(C_*C_+255)/256, 256>>>(proj_w, p_w16, C_*C_);
    tc_gemm<<<dim3(C_/128, M_/128), 256>>>(p_a16, p_w16, proj_b, p_xt, p_xt2, C_, C_);

    k_ln_lif<<<ROWS_PER_T, C_>>>(p_xt2, p_h16, ln2_g, ln2_b, lif_w, 6);

    k_f2h<<<(HID_*C_+255)/256, 256>>>(fc1_w, p_w16, HID_*C_);
    tc_gemm<<<dim3(HID_/128, M_/128), 256>>>(p_h16, p_w16, fc1_b, nullptr, p_mlp, HID_, C_);

    k_lif_seq_h<<<(ROWS_PER_T*HID_+255)/256, 256>>>(p_mlp, p_m16, (size_t)ROWS_PER_T*HID_, lif_w, 7);

    k_f2h<<<(C_*HID_+255)/256, 256>>>(fc2_w, p_w16, C_*HID_);
    tc_gemm<<<dim3(C_/128, M_/128), 256>>>(p_m16, p_w16, fc2_b, p_xt2, p_xt, C_, HID_);

    k_tr_out<<<dim3(C_/32, N_/32, T_*B_), dim3(32,8)>>>(out);
}

// round 4
// speedup vs baseline: 4.7235x; 1.1802x over previous
#include <cuda_runtime.h>
#include <cuda_fp16.h>
#include <math.h>
#include <stdint.h>

// ---------------- problem constants ----------------
#define T_  4
#define B_  16
#define C_  512
#define H_  16
#define W_  16
#define N_  256
#define NH_ 8
#define D_  64
#define M_  (T_*B_*N_)     // 16384
#define HID_ 2048
#define ROWS_PER_T (B_*N_) // 4096

// ---------------- scratch ----------------
__device__ float  g_xt [M_*C_];          // tokens (phys t-order rows)
__device__ float  g_xt2[M_*C_];
__device__ float  g_kv [T_*B_*NH_*D_*D_]; // 512 * 4096 fp32
__device__ __half g_h16[M_*C_];          // LN spikes
__device__ __half g_q16[M_*3*C_];        // qkv spikes
__device__ __half g_a16[M_*C_];          // attention spikes
__device__ __half g_m16[M_*HID_];        // mlp spikes
__device__ __half g_w16[HID_*C_];        // weight fp16

__device__ __forceinline__ float sigm(float w){ return 1.0f/(1.0f+expf(-w)); }
__device__ __forceinline__ uint32_t s2u(const void* p){
    uint32_t a;
    asm("{ .reg .u64 t; cvta.to.shared.u64 t, %1; cvt.u32.u64 %0, t; }" : "=r"(a) : "l"(p));
    return a;
}
__device__ __forceinline__ void cp16(uint32_t s, const void* g){
    asm volatile("cp.async.cg.shared.global [%0], [%1], 16;" :: "r"(s), "l"(g));
}
__device__ __forceinline__ void ldsm4(uint32_t* r, uint32_t addr){
    asm volatile("ldmatrix.sync.aligned.m8n8.x4.shared.b16 {%0,%1,%2,%3}, [%4];"
                 : "=r"(r[0]), "=r"(r[1]), "=r"(r[2]), "=r"(r[3]) : "r"(addr));
}
__device__ __forceinline__ void mma16816(float* c, const uint32_t* a, uint32_t b0, uint32_t b1){
    asm volatile(
        "mma.sync.aligned.m16n8k16.row.col.f32.f16.f16.f32 "
        "{%0,%1,%2,%3}, {%4,%5,%6,%7}, {%8,%9}, {%0,%1,%2,%3};"
        : "+f"(c[0]), "+f"(c[1]), "+f"(c[2]), "+f"(c[3])
        : "r"(a[0]), "r"(a[1]), "r"(a[2]), "r"(a[3]), "r"(b0), "r"(b1));
}

// ---------------- HMMA GEMM with logical row remap + optional fused LIF -----
// logical row r = bn*4 + t  <->  phys row = (r&3)*4096 + (r>>2)
// MODE 0: fp32 out + bias + residual (proj, fc2)
// MODE 1: fused LIF, per-512-col decay lifw[2..4], fp16 spike out (qkv)
// MODE 2: fused LIF, decay lifw[7], bias, fp16 spike out (fc1)
#define LDT 40
#define STG 132

template<int MODE>
__global__ void __launch_bounds__(256) tc_gemm(
        const __half* __restrict__ A, const __half* __restrict__ Wt,
        const float* __restrict__ bias, const float* __restrict__ res,
        float* __restrict__ outf, __half* __restrict__ outh,
        const float* __restrict__ lifw, int Ndim, int K){
    extern __shared__ char smraw[];
    __half* sA = (__half*)smraw;                              // [2][128*LDT]
    __half* sB = (__half*)(smraw + 2*128*LDT*sizeof(__half));
    float*  stage = (float*)smraw;                            // reused (MODE!=0)

    int tid = threadIdx.x;
    int warp = tid >> 5, lane = tid & 31;
    int wm = (warp & 1) * 64;
    int wn = (warp >> 1) * 32;
    int bm = blockIdx.y * 128, bn = blockIdx.x * 128;
    float acc[4][4][4] = {};

    int l8 = lane >> 3;
    int arow = (lane & 7) + (l8 & 1) * 8;
    int acol = (l8 >> 1) * 8;
    int brow = (lane & 7) + (l8 >> 1) * 8;
    int bcol = (l8 & 1) * 8;

    const int NC = K / 32;
    // prologue load
    {
        #pragma unroll
        for (int it = 0; it < 2; it++){
            int task = tid + it*256;
            int row = task >> 2, ch = task & 3;
            int pr = (row & 3)*ROWS_PER_T + (bm >> 2) + (row >> 2);
            cp16(s2u(&sA[row*LDT + ch*8]), A  + (size_t)pr*K + ch*8);
            cp16(s2u(&sB[row*LDT + ch*8]), Wt + (size_t)(bn+row)*K + ch*8);
        }
        asm volatile("cp.async.commit_group;");
    }

    for (int c = 0; c < NC; c++){
        int buf = c & 1;
        asm volatile("cp.async.wait_group 0;" ::: "memory");
        __syncthreads();
        if (c + 1 < NC){
            int nb = buf ^ 1, k0 = (c+1)*32;
            #pragma unroll
            for (int it = 0; it < 2; it++){
                int task = tid + it*256;
                int row = task >> 2, ch = task & 3;
                int pr = (row & 3)*ROWS_PER_T + (bm >> 2) + (row >> 2);
                cp16(s2u(&sA[nb*128*LDT + row*LDT + ch*8]), A  + (size_t)pr*K + k0 + ch*8);
                cp16(s2u(&sB[nb*128*LDT + row*LDT + ch*8]), Wt + (size_t)(bn+row)*K + k0 + ch*8);
            }
            asm volatile("cp.async.commit_group;");
        }
        #pragma unroll
        for (int ks = 0; ks < 2; ks++){
            uint32_t af[4][4], bf[2][4];
            #pragma unroll
            for (int mi = 0; mi < 4; mi++)
                ldsm4(af[mi], s2u(&sA[buf*128*LDT + (wm + mi*16 + arow)*LDT + ks*16 + acol]));
            #pragma unroll
            for (int np = 0; np < 2; np++)
                ldsm4(bf[np], s2u(&sB[buf*128*LDT + (wn + np*16 + brow)*LDT + ks*16 + bcol]));
            #pragma unroll
            for (int mi = 0; mi < 4; mi++)
                #pragma unroll
                for (int ni = 0; ni < 4; ni++)
                    mma16816(acc[mi][ni], af[mi],
                             bf[ni>>1][2*(ni&1)], bf[ni>>1][2*(ni&1)+1]);
        }
        __syncthreads();
    }

    int g = lane >> 2, i2 = (lane & 3) * 2;
    if (MODE == 0){
        #pragma unroll
        for (int mi = 0; mi < 4; mi++){
            int rl0 = bm + wm + mi*16 + g;
            int rl1 = rl0 + 8;
            int rp0 = (rl0 & 3)*ROWS_PER_T + (rl0 >> 2);
            int rp1 = (rl1 & 3)*ROWS_PER_T + (rl1 >> 2);
            #pragma unroll
            for (int ni = 0; ni < 4; ni++){
                int col = bn + wn + ni*8 + i2;
                float b0 = bias ? bias[col]   : 0.f;
                float b1 = bias ? bias[col+1] : 0.f;
                float v00 = acc[mi][ni][0] + b0, v01 = acc[mi][ni][1] + b1;
                float v10 = acc[mi][ni][2] + b0, v11 = acc[mi][ni][3] + b1;
                size_t o0 = (size_t)rp0*Ndim + col;
                size_t o1 = (size_t)rp1*Ndim + col;
                if (res){
                    v00 += res[o0]; v01 += res[o0+1];
                    v10 += res[o1]; v11 += res[o1+1];
                }
                *(float2*)&outf[o0] = make_float2(v00, v01);
                *(float2*)&outf[o1] = make_float2(v10, v11);
            }
        }
    } else {
        // stage fp32 tile to smem, then LIF over 4-row t-groups
        #pragma unroll
        for (int mi = 0; mi < 4; mi++){
            int r0 = wm + mi*16 + g, r1 = r0 + 8;
            #pragma unroll
            for (int ni = 0; ni < 4; ni++){
                int cl = wn + ni*8 + i2;
                stage[r0*STG + cl]   = acc[mi][ni][0];
                stage[r0*STG + cl+1] = acc[mi][ni][1];
                stage[r1*STG + cl]   = acc[mi][ni][2];
                stage[r1*STG + cl+1] = acc[mi][ni][3];
            }
        }
        __syncthreads();
        float d0, d1 = 0.f, d2 = 0.f;
        if (MODE == 1){ d0 = sigm(lifw[2]); d1 = sigm(lifw[3]); d2 = sigm(lifw[4]); }
        else          { d0 = sigm(lifw[7]); }
        #pragma unroll
        for (int it = 0; it < 16; it++){
            int chain = tid + it*256;
            int col = chain & 127, bnl = chain >> 7;
            int gcol = bn + col;
            float bi = bias ? bias[gcol] : 0.f;
            float dec = (MODE == 1) ? (gcol < 512 ? d0 : (gcol < 1024 ? d1 : d2)) : d0;
            float v = 0.f;
            #pragma unroll
            for (int t = 0; t < 4; t++){
                float xv = stage[(bnl*4 + t)*STG + col] + bi;
                v += (xv - v)*dec;
                float sp = (v >= 1.0f) ? 1.f : 0.f;
                int pr = t*ROWS_PER_T + (bm >> 2) + bnl;
                outh[(size_t)pr*Ndim + gcol] = __float2half_rn(sp);
                if (sp > 0.f) v = 0.f;
            }
        }
    }
}

// ---------------- fused input-LIF + depthwise conv + residual ---------------
// block: b = blk>>5, c0 = (blk&31)*16; 256 threads.
__global__ void __launch_bounds__(256) k_conv_lif(
        const float* __restrict__ x, const float* __restrict__ cw,
        const float* __restrict__ cb, const float* __restrict__ lifw){
    __shared__ float  xs[16*257];
    __shared__ __half sp[16*264];
    __shared__ float  ws[16*9];
    __shared__ float  wb[16];
    int tid = threadIdx.x;
    int b  = blockIdx.x >> 5;
    int c0 = (blockIdx.x & 31) * 16;
    if (tid < 16*9) ws[tid] = cw[c0*9 + tid];
    if (tid < 16)   wb[tid] = cb[c0 + tid];
    float dec = sigm(lifw[0]);
    float v[16];
    #pragma unroll
    for (int i = 0; i < 16; i++) v[i] = 0.f;
    __syncthreads();
    for (int t = 0; t < T_; t++){
        int tb = t*B_ + b;
        #pragma unroll
        for (int i = 0; i < 16; i++){
            int lin = tid + i*256;
            int cl = lin >> 8, px = lin & 255;
            float xv = x[((size_t)tb*C_ + c0 + cl)*256 + px];
            xs[cl*257 + px] = xv;
            float vv = v[i] + (xv - v[i])*dec;
            float s = (vv >= 1.0f) ? 1.f : 0.f;
            v[i] = (s > 0.f) ? 0.f : vv;
            sp[cl*264 + px] = __float2half_rn(s);
        }
        __syncthreads();
        #pragma unroll
        for (int i = 0; i < 16; i++){
            int lin = tid + i*256;
            int cl = lin & 15, n = lin >> 4;
            int hh = n >> 4, wp = n & 15;
            float acc = wb[cl];
            const float* wk = &ws[cl*9];
            #pragma unroll
            for (int kh = 0; kh < 3; kh++){
                int h2 = hh + kh - 1;
                if (h2 < 0 || h2 > 15) continue;
                #pragma unroll
                for (int kw = 0; kw < 3; kw++){
                    int w2 = wp + kw - 1;
                    if (w2 < 0 || w2 > 15) continue;
                    acc += __half2float(sp[cl*264 + h2*16 + w2]) * wk[kh*3 + kw];
                }
            }
            float val = xs[cl*257 + n] + acc;
            g_xt[((size_t)tb*256 + n)*C_ + c0 + cl] = val;
        }
        __syncthreads();
    }
}

// ---------------- LayerNorm + LIF, warp-per-token ---------------------------
__global__ void __launch_bounds__(256) k_ln_lif(
        const float* __restrict__ in, __half* __restrict__ out,
        const float* __restrict__ gam, const float* __restrict__ bet,
        const float* __restrict__ lifw, int lidx){
    int tid = threadIdx.x, wid = tid >> 5, lane = tid & 31;
    int bn = blockIdx.x*8 + wid;
    int cb = lane*16;
    float dec = sigm(lifw[lidx]);
    float gg[16], bb[16];
    #pragma unroll
    for (int i = 0; i < 4; i++){
        float4 t1 = *(const float4*)&gam[cb + i*4];
        float4 t2 = *(const float4*)&bet[cb + i*4];
        gg[i*4]=t1.x; gg[i*4+1]=t1.y; gg[i*4+2]=t1.z; gg[i*4+3]=t1.w;
        bb[i*4]=t2.x; bb[i*4+1]=t2.y; bb[i*4+2]=t2.z; bb[i*4+3]=t2.w;
    }
    float v[16];
    #pragma unroll
    for (int i = 0; i < 16; i++) v[i] = 0.f;
    for (int t = 0; t < T_; t++){
        int row = t*ROWS_PER_T + bn;
        const float* xr = in + (size_t)row*C_ + cb;
        float xv[16];
        #pragma unroll
        for (int i = 0; i < 4; i++){
            float4 x4 = *(const float4*)&xr[i*4];
            xv[i*4]=x4.x; xv[i*4+1]=x4.y; xv[i*4+2]=x4.z; xv[i*4+3]=x4.w;
        }
        float s = 0.f, ss = 0.f;
        #pragma unroll
        for (int i = 0; i < 16; i++){ s += xv[i]; ss += xv[i]*xv[i]; }
        #pragma unroll
        for (int o = 16; o > 0; o >>= 1){
            s  += __shfl_xor_sync(0xffffffffu, s,  o);
            ss += __shfl_xor_sync(0xffffffffu, ss, o);
        }
        float mean = s*(1.0f/C_);
        float var  = ss*(1.0f/C_) - mean*mean;
        float rstd = rsqrtf(var + 1e-5f);
        union { __half h[16]; uint4 u[2]; } pk;
        #pragma unroll
        for (int k = 0; k < 16; k++){
            float ln = (xv[k]-mean)*rstd*gg[k] + bb[k];
            v[k] += (ln - v[k])*dec;
            float spv = (v[k] >= 1.0f) ? 1.f : 0.f;
            pk.h[k] = __float2half_rn(spv);
            if (spv > 0.f) v[k] = 0.f;
        }
        uint4* dst = (uint4*)(out + (size_t)row*C_ + cb);
        dst[0] = pk.u[0]; dst[1] = pk.u[1];
    }
}

// ---------------- attention phase 1: kv = k^T v per (t,b,h) -----------------
__global__ void __launch_bounds__(256) k_attn_kv(){
    int blk = blockIdx.x;            // 512
    int h  = blk & (NH_-1);
    int tb = blk >> 3;
    __shared__ float ks[64*64];
    __shared__ float vs[64*64];
    int tid = threadIdx.x;
    int ti = tid >> 4, tj = tid & 15;
    float acc[4][4] = {};
    const __half* base = g_q16 + (size_t)tb*256*(3*C_);
    for (int n0 = 0; n0 < N_; n0 += 64){
        int tok = tid >> 2, doff = (tid & 3)*16;
        const __half* kr = base + (size_t)(n0+tok)*(3*C_) + C_   + h*D_ + doff;
        const __half* vr = base + (size_t)(n0+tok)*(3*C_) + 2*C_ + h*D_ + doff;
        #pragma unroll
        for (int i = 0; i < 16; i++){
            ks[tok*64 + doff + i] = __half2float(kr[i]);
            vs[tok*64 + doff + i] = __half2float(vr[i]);
        }
        __syncthreads();
        #pragma unroll 8
        for (int nn = 0; nn < 64; nn++){
            float ra[4], rb[4];
            #pragma unroll
            for (int i = 0; i < 4; i++) ra[i] = ks[nn*64 + ti*4 + i];
            #pragma unroll
            for (int j = 0; j < 4; j++) rb[j] = vs[nn*64 + tj*4 + j];
            #pragma unroll
            for (int i = 0; i < 4; i++)
                #pragma unroll
                for (int j = 0; j < 4; j++)
                    acc[i][j] += ra[i]*rb[j];
        }
        __syncthreads();
    }
    float* dst = g_kv + (size_t)blk*4096;
    #pragma unroll
    for (int i = 0; i < 4; i++)
        #pragma unroll
        for (int j = 0; j < 4; j++)
            dst[(ti*4+i)*64 + tj*4+j] = acc[i][j];
}

// ---------------- attention phase 2: a = q@kv*scale + LIF -> fp16 spikes ----
__global__ void __launch_bounds__(256) k_attn_av(const float* __restrict__ lifw){
    int blk = blockIdx.x;            // 128 = B*NH
    int h = blk & (NH_-1);
    int b = blk >> 3;
    __shared__ float kvs[64*64];
    int tid = threadIdx.x;           // token n
    float dec = sigm(lifw[5]);
    float v[64];
    #pragma unroll
    for (int j = 0; j < 64; j++) v[j] = 0.f;
    for (int t = 0; t < T_; t++){
        int tb = t*B_ + b;
        const float* kvsrc = g_kv + (size_t)(tb*NH_ + h)*4096;
        #pragma unroll
        for (int i = 0; i < 16; i++)
            kvs[tid + i*256] = kvsrc[tid + i*256];
        __syncthreads();
        int row = tb*256 + tid;
        const __half2* qp = (const __half2*)(g_q16 + (size_t)row*(3*C_) + h*D_);
        half2 q[32];
        #pragma unroll
        for (int i = 0; i < 32; i++) q[i] = qp[i];
        #pragma unroll
        for (int jc = 0; jc < 8; jc++){
            float s[8] = {};
            #pragma unroll 8
            for (int i2 = 0; i2 < 32; i2++){
                float2 qf = __half22float2(q[i2]);
                #pragma unroll
                for (int j = 0; j < 8; j++){
                    s[j] += qf.x*kvs[(2*i2)*64 + jc*8 + j];
                    s[j] += qf.y*kvs[(2*i2+1)*64 + jc*8 + j];
                }
            }
            union { __half hh[8]; uint4 u; } pk;
            #pragma unroll
            for (int j = 0; j < 8; j++){
                int jj = jc*8 + j;
                float a = s[j]*0.125f;
                v[jj] += (a - v[jj])*dec;
                float sp = (v[jj] >= 1.0f) ? 1.f : 0.f;
                pk.hh[j] = __float2half_rn(sp);
                if (sp > 0.f) v[jj] = 0.f;
            }
            *(uint4*)(g_a16 + (size_t)row*C_ + h*D_ + jc*8) = pk.u;
        }
        __syncthreads();
    }
}

// ---------------- f32 -> f16 convert (vec4) ---------------------------------
__global__ void k_f2h4(const float* __restrict__ in, __half* __restrict__ out, int n4){
    int i = blockIdx.x*blockDim.x + threadIdx.x;
    if (i >= n4) return;
    float4 f = *(const float4*)&in[i*4];
    union { __half h[4]; uint2 u; } pk;
    pk.h[0]=__float2half_rn(f.x); pk.h[1]=__float2half_rn(f.y);
    pk.h[2]=__float2half_rn(f.z); pk.h[3]=__float2half_rn(f.w);
    *(uint2*)&out[i*4] = pk.u;
}

// ---------------- tokens [tb, N, C] -> output [tb, C, N] --------------------
__global__ void k_tr_out(float* __restrict__ out){
    __shared__ float tile[32][33];
    int tb = blockIdx.z;
    int n0 = blockIdx.y*32, c0 = blockIdx.x*32;
    const float* src = g_xt + (size_t)tb*N_*C_;
    float* dst = out + (size_t)tb*C_*N_;
    int tx = threadIdx.x, ty = threadIdx.y;
    #pragma unroll
    for (int r = 0; r < 32; r += 8)
        tile[ty+r][tx] = src[(size_t)(n0+ty+r)*C_ + c0+tx];
    __syncthreads();
    #pragma unroll
    for (int r = 0; r < 32; r += 8)
        dst[(size_t)(c0+ty+r)*N_ + n0+tx] = tile[tx][ty+r];
}

// ---------------- host orchestration ----------------------------------------
extern "C" void kernel_launch(void* const* d_in, const int* in_sizes, int n_in,
                              void* d_out, int out_size){
    const float* x      = (const float*)d_in[0];
    const float* conv_w = (const float*)d_in[1];
    const float* conv_b = (const float*)d_in[2];
    const float* ln1_g  = (const float*)d_in[3];
    const float* ln1_b  = (const float*)d_in[4];
    const float* qkv_w  = (const float*)d_in[5];
    const float* proj_w = (const float*)d_in[6];
    const float* proj_b = (const float*)d_in[7];
    const float* ln2_g  = (const float*)d_in[8];
    const float* ln2_b  = (const float*)d_in[9];
    const float* fc1_w  = (const float*)d_in[10];
    const float* fc1_b  = (const float*)d_in[11];
    const float* fc2_w  = (const float*)d_in[12];
    const float* fc2_b  = (const float*)d_in[13];
    const float* lif_w  = (const float*)d_in[14];
    float* out = (float*)d_out;

    const int SM_STD = 2*2*128*LDT*(int)sizeof(__half);        // 40960
    const int SM_LIF = 128*STG*(int)sizeof(float);             // 67584
    cudaFuncSetAttribute(tc_gemm<1>, cudaFuncAttributeMaxDynamicSharedMemorySize, SM_LIF);
    cudaFuncSetAttribute(tc_gemm<2>, cudaFuncAttributeMaxDynamicSharedMemorySize, SM_LIF);

    float *p_xt, *p_xt2;
    __half *p_h16, *p_q16, *p_a16, *p_m16, *p_w16;
    cudaGetSymbolAddress((void**)&p_xt,  g_xt);
    cudaGetSymbolAddress((void**)&p_xt2, g_xt2);
    cudaGetSymbolAddress((void**)&p_h16, g_h16);
    cudaGetSymbolAddress((void**)&p_q16, g_q16);
    cudaGetSymbolAddress((void**)&p_a16, g_a16);
    cudaGetSymbolAddress((void**)&p_m16, g_m16);
    cudaGetSymbolAddress((void**)&p_w16, g_w16);

    // 1. fused input LIF + conv + residual -> g_xt
    k_conv_lif<<<512, 256>>>(x, conv_w, conv_b, lif_w);
    // 2. LN1 + LIF -> g_h16
    k_ln_lif<<<512, 256>>>(p_xt, p_h16, ln1_g, ln1_b, lif_w, 1);
    // 3. qkv GEMM + fused qkv-LIF -> g_q16 spikes
    k_f2h4<<<(3*C_*C_/4+255)/256, 256>>>(qkv_w, p_w16, 3*C_*C_/4);
    tc_gemm<1><<<dim3(12,128), 256, SM_LIF>>>(p_h16, p_w16, nullptr, nullptr,
                                              nullptr, p_q16, lif_w, 3*C_, C_);
    // 4. attention
    k_attn_kv<<<512, 256>>>();
    k_attn_av<<<128, 256>>>(lif_w);
    // 5. proj GEMM + bias + residual -> g_xt2
    k_f2h4<<<(C_*C_/4+255)/256, 256>>>(proj_w, p_w16, C_*C_/4);
    tc_gemm<0><<<dim3(4,128), 256, SM_STD>>>(p_a16, p_w16, proj_b, p_xt,
                                             p_xt2, nullptr, lif_w, C_, C_);
    // 6. LN2 + LIF -> g_h16
    k_ln_lif<<<512, 256>>>(p_xt2, p_h16, ln2_g, ln2_b, lif_w, 6);
    // 7. fc1 GEMM + bias + fused mlp-LIF -> g_m16
    k_f2h4<<<(HID_*C_/4+255)/256, 256>>>(fc1_w, p_w16, HID_*C_/4);
    tc_gemm<2><<<dim3(16,128), 256, SM_LIF>>>(p_h16, p_w16, fc1_b, nullptr,
                                              nullptr, p_m16, lif_w, HID_, C_);
    // 8. fc2 GEMM + bias + residual -> g_xt
    k_f2h4<<<(C_*HID_/4+255)/256, 256>>>(fc2_w, p_w16, C_*HID_/4);
    tc_gemm<0><<<dim3(4,128), 256, SM_STD>>>(p_m16, p_w16, fc2_b, p_xt2,
                                             p_xt, nullptr, lif_w, C_, HID_);
    // 9. transpose to output layout
    k_tr_out<<<dim3(C_/32, N_/32, T_*B_), dim3(32,8)>>>(out);
}

// round 5
// speedup vs baseline: 5.3741x; 1.1378x over previous
#include <cuda_runtime.h>
#include <cuda_fp16.h>
#include <math.h>
#include <stdint.h>

// ---------------- problem constants ----------------
#define T_  4
#define B_  16
#define C_  512
#define H_  16
#define W_  16
#define N_  256
#define NH_ 8
#define D_  64
#define M_  (T_*B_*N_)     // 16384
#define HID_ 2048
#define ROWS_PER_T (B_*N_) // 4096

// ---------------- scratch ----------------
__device__ float  g_xt [M_*C_];
__device__ float  g_xt2[M_*C_];
__device__ float  g_kv [T_*B_*NH_*D_*D_];
__device__ __half g_h16[M_*C_];
__device__ __half g_q16[M_*3*C_];
__device__ __half g_a16[M_*C_];
__device__ __half g_m16[M_*HID_];
__device__ __half g_wall[3*C_*C_ + C_*C_ + 2*HID_*C_];  // qkv|proj|fc1|fc2 fp16

#define WOFF_QKV  0
#define WOFF_PROJ (3*C_*C_)
#define WOFF_FC1  (WOFF_PROJ + C_*C_)
#define WOFF_FC2  (WOFF_FC1 + HID_*C_)

__device__ __forceinline__ float sigm(float w){ return 1.0f/(1.0f+expf(-w)); }
__device__ __forceinline__ uint32_t s2u(const void* p){
    uint32_t a;
    asm("{ .reg .u64 t; cvta.to.shared.u64 t, %1; cvt.u32.u64 %0, t; }" : "=r"(a) : "l"(p));
    return a;
}
__device__ __forceinline__ void cp16(uint32_t s, const void* g){
    asm volatile("cp.async.cg.shared.global [%0], [%1], 16;" :: "r"(s), "l"(g));
}
__device__ __forceinline__ void ldsm4(uint32_t* r, uint32_t addr){
    asm volatile("ldmatrix.sync.aligned.m8n8.x4.shared.b16 {%0,%1,%2,%3}, [%4];"
                 : "=r"(r[0]), "=r"(r[1]), "=r"(r[2]), "=r"(r[3]) : "r"(addr));
}
__device__ __forceinline__ void mma16816(float* c, const uint32_t* a, uint32_t b0, uint32_t b1){
    asm volatile(
        "mma.sync.aligned.m16n8k16.row.col.f32.f16.f16.f32 "
        "{%0,%1,%2,%3}, {%4,%5,%6,%7}, {%8,%9}, {%0,%1,%2,%3};"
        : "+f"(c[0]), "+f"(c[1]), "+f"(c[2]), "+f"(c[3])
        : "r"(a[0]), "r"(a[1]), "r"(a[2]), "r"(a[3]), "r"(b0), "r"(b1));
}

// ---------------- HMMA GEMM, 4-stage pipeline, logical row remap ------------
// logical row r = bn_token*4 + t  <->  phys row = (r&3)*4096 + (r>>2)
// MODE 0: fp32 out + bias + residual (proj)
// MODE 1: fused LIF per-512-col decay lifw[2..4] -> fp16 spikes (qkv)
// MODE 2: fused LIF decay lifw[7] + bias -> fp16 spikes (fc1)
// MODE 3: bias + residual, write fp32 transposed [T,B,C,N] direct to output (fc2)
#define LDT 40
#define S_  4
#define STAGE_BYTES (128*LDT*2)       // 10240
#define GEMM_SMEM (S_*2*STAGE_BYTES)  // 81920
#define STG  132                       // MODE1/2 stage row stride (floats)
#define STG3 133                       // MODE3 (odd: halves gather conflicts)

template<int MODE>
__global__ void __launch_bounds__(256) tc_gemm(
        const __half* __restrict__ A, const __half* __restrict__ Wt,
        const float* __restrict__ bias, const float* __restrict__ res,
        float* __restrict__ outf, __half* __restrict__ outh,
        const float* __restrict__ lifw, int Ndim, int K){
    extern __shared__ char smraw[];
    float* stage = (float*)smraw;
    uint32_t sAu = s2u(smraw);
    uint32_t sBu = sAu + S_*STAGE_BYTES;

    int tid = threadIdx.x;
    int warp = tid >> 5, lane = tid & 31;
    int wm = (warp & 1) * 64;
    int wn = (warp >> 1) * 32;
    int bm = blockIdx.y * 128, bn = blockIdx.x * 128;
    float acc[4][4][4] = {};

    // per-thread load tasks (2): row = task>>2, ch = task&3
    const __half* ga[2]; const __half* gb[2];
    uint32_t so[2];
    #pragma unroll
    for (int it = 0; it < 2; it++){
        int task = tid + it*256;
        int row = task >> 2, ch = task & 3;
        int pr = (row & 3)*ROWS_PER_T + (bm >> 2) + (row >> 2);
        ga[it] = A  + (size_t)pr*K + ch*8;
        gb[it] = Wt + (size_t)(bn+row)*K + ch*8;
        so[it] = (uint32_t)((row*LDT + ch*8)*2);
    }

    const int NC = K / 32;
    #pragma unroll
    for (int p = 0; p < S_-1; p++){
        #pragma unroll
        for (int it = 0; it < 2; it++){
            cp16(sAu + p*STAGE_BYTES + so[it], ga[it] + p*32);
            cp16(sBu + p*STAGE_BYTES + so[it], gb[it] + p*32);
        }
        asm volatile("cp.async.commit_group;");
    }

    // ldsm base addresses
    int l8 = lane >> 3;
    int arow = (lane & 7) + (l8 & 1) * 8, acol = (l8 >> 1) * 8;
    int brow = (lane & 7) + (l8 >> 1) * 8, bcol = (l8 & 1) * 8;
    uint32_t abase[4], bbase[2];
    #pragma unroll
    for (int mi = 0; mi < 4; mi++)
        abase[mi] = sAu + ((wm + mi*16 + arow)*LDT + acol)*2;
    #pragma unroll
    for (int np = 0; np < 2; np++)
        bbase[np] = sBu + ((wn + np*16 + brow)*LDT + bcol)*2;

    for (int c = 0; c < NC; c++){
        uint32_t stoff = (uint32_t)(c % S_) * STAGE_BYTES;
        asm volatile("cp.async.wait_group 2;" ::: "memory");
        __syncthreads();
        if (c + S_-1 < NC){
            uint32_t poff = (uint32_t)((c + S_-1) % S_) * STAGE_BYTES;
            const __half* gaoff = (const __half*)((const char*)0 + (size_t)(c+S_-1)*64);
            (void)gaoff;
            #pragma unroll
            for (int it = 0; it < 2; it++){
                cp16(sAu + poff + so[it], ga[it] + (c+S_-1)*32);
                cp16(sBu + poff + so[it], gb[it] + (c+S_-1)*32);
            }
        }
        asm volatile("cp.async.commit_group;");
        #pragma unroll
        for (int ks = 0; ks < 2; ks++){
            uint32_t af[4][4], bf[2][4];
            #pragma unroll
            for (int mi = 0; mi < 4; mi++)
                ldsm4(af[mi], abase[mi] + stoff + ks*32);
            #pragma unroll
            for (int np = 0; np < 2; np++)
                ldsm4(bf[np], bbase[np] + stoff + ks*32);
            #pragma unroll
            for (int mi = 0; mi < 4; mi++)
                #pragma unroll
                for (int ni = 0; ni < 4; ni++)
                    mma16816(acc[mi][ni], af[mi],
                             bf[ni>>1][2*(ni&1)], bf[ni>>1][2*(ni&1)+1]);
        }
    }

    int g = lane >> 2, i2 = (lane & 3) * 2;
    if (MODE == 0){
        #pragma unroll
        for (int mi = 0; mi < 4; mi++){
            int rl0 = bm + wm + mi*16 + g;
            int rl1 = rl0 + 8;
            int rp0 = (rl0 & 3)*ROWS_PER_T + (rl0 >> 2);
            int rp1 = (rl1 & 3)*ROWS_PER_T + (rl1 >> 2);
            #pragma unroll
            for (int ni = 0; ni < 4; ni++){
                int col = bn + wn + ni*8 + i2;
                float b0 = bias ? bias[col]   : 0.f;
                float b1 = bias ? bias[col+1] : 0.f;
                float v00 = acc[mi][ni][0] + b0, v01 = acc[mi][ni][1] + b1;
                float v10 = acc[mi][ni][2] + b0, v11 = acc[mi][ni][3] + b1;
                size_t o0 = (size_t)rp0*Ndim + col;
                size_t o1 = (size_t)rp1*Ndim + col;
                if (res){
                    v00 += res[o0]; v01 += res[o0+1];
                    v10 += res[o1]; v11 += res[o1+1];
                }
                *(float2*)&outf[o0] = make_float2(v00, v01);
                *(float2*)&outf[o1] = make_float2(v10, v11);
            }
        }
    } else if (MODE == 1 || MODE == 2){
        __syncthreads();
        #pragma unroll
        for (int mi = 0; mi < 4; mi++){
            int r0 = wm + mi*16 + g, r1 = r0 + 8;
            #pragma unroll
            for (int ni = 0; ni < 4; ni++){
                int cl = wn + ni*8 + i2;
                *(float2*)&stage[r0*STG + cl] = make_float2(acc[mi][ni][0], acc[mi][ni][1]);
                *(float2*)&stage[r1*STG + cl] = make_float2(acc[mi][ni][2], acc[mi][ni][3]);
            }
        }
        __syncthreads();
        float d0, d1 = 0.f, d2 = 0.f;
        if (MODE == 1){ d0 = sigm(lifw[2]); d1 = sigm(lifw[3]); d2 = sigm(lifw[4]); }
        else          { d0 = sigm(lifw[7]); }
        #pragma unroll
        for (int it = 0; it < 2; it++){
            int t2 = tid + it*256;
            int bnl = t2 >> 4, cg = (t2 & 15) * 8;
            int gc = bn + cg;
            float dec = (MODE == 1) ? (gc < 512 ? d0 : (gc < 1024 ? d1 : d2)) : d0;
            float bi[8];
            if (bias){
                float4 q0 = *(const float4*)&bias[gc];
                float4 q1 = *(const float4*)&bias[gc+4];
                bi[0]=q0.x; bi[1]=q0.y; bi[2]=q0.z; bi[3]=q0.w;
                bi[4]=q1.x; bi[5]=q1.y; bi[6]=q1.z; bi[7]=q1.w;
            } else {
                #pragma unroll
                for (int j = 0; j < 8; j++) bi[j] = 0.f;
            }
            float v[8];
            #pragma unroll
            for (int j = 0; j < 8; j++) v[j] = 0.f;
            #pragma unroll
            for (int t = 0; t < 4; t++){
                int r = bnl*4 + t;
                float4 x0 = *(float4*)&stage[r*STG + cg];
                float4 x1 = *(float4*)&stage[r*STG + cg + 4];
                float xv[8] = {x0.x,x0.y,x0.z,x0.w,x1.x,x1.y,x1.z,x1.w};
                union { __half h[8]; uint4 u; } pk;
                #pragma unroll
                for (int j = 0; j < 8; j++){
                    float xx = xv[j] + bi[j];
                    v[j] += (xx - v[j])*dec;
                    float sp = (v[j] >= 1.0f) ? 1.f : 0.f;
                    pk.h[j] = __float2half_rn(sp);
                    if (sp > 0.f) v[j] = 0.f;
                }
                int pr = t*ROWS_PER_T + (bm >> 2) + bnl;
                *(uint4*)&outh[(size_t)pr*Ndim + gc] = pk.u;
            }
        }
    } else {
        // MODE 3: bias + residual, write transposed [T,B,C,N] to outf
        __syncthreads();
        #pragma unroll
        for (int mi = 0; mi < 4; mi++){
            int r0 = wm + mi*16 + g, r1 = r0 + 8;
            int rl0 = bm + r0, rl1 = bm + r1;
            int rp0 = (rl0 & 3)*ROWS_PER_T + (rl0 >> 2);
            int rp1 = (rl1 & 3)*ROWS_PER_T + (rl1 >> 2);
            #pragma unroll
            for (int ni = 0; ni < 4; ni++){
                int cl = wn + ni*8 + i2;
                int col = bn + cl;
                float b0 = bias[col], b1 = bias[col+1];
                size_t o0 = (size_t)rp0*Ndim + col;
                size_t o1 = (size_t)rp1*Ndim + col;
                stage[r0*STG3 + cl]   = acc[mi][ni][0] + b0 + res[o0];
                stage[r0*STG3 + cl+1] = acc[mi][ni][1] + b1 + res[o0+1];
                stage[r1*STG3 + cl]   = acc[mi][ni][2] + b0 + res[o1];
                stage[r1*STG3 + cl+1] = acc[mi][ni][3] + b1 + res[o1+1];
            }
        }
        __syncthreads();
        int btok = bm >> 2;
        int b = btok >> 8, n0 = btok & 255;
        #pragma unroll
        for (int it = 0; it < 16; it++){
            int f4 = tid + it*256;        // 0..4095
            int rown = f4 >> 3;           // 0..511 : c = rown>>2, t = rown&3
            int n4 = f4 & 7;
            int cc = rown >> 2, t = rown & 3;
            float4 val;
            val.x = stage[((n4*4+0)*4 + t)*STG3 + cc];
            val.y = stage[((n4*4+1)*4 + t)*STG3 + cc];
            val.z = stage[((n4*4+2)*4 + t)*STG3 + cc];
            val.w = stage[((n4*4+3)*4 + t)*STG3 + cc];
            size_t dst = ((size_t)(t*B_ + b)*C_ + bn + cc)*N_ + n0 + n4*4;
            *(float4*)&outf[dst] = val;
        }
    }
}

// ---------------- all-weights f32 -> f16 convert ----------------------------
__global__ void k_f2hall(const float* __restrict__ w0, const float* __restrict__ w1,
                         const float* __restrict__ w2, const float* __restrict__ w3){
    int i = blockIdx.x*blockDim.x + threadIdx.x;   // float4 task, 786432 total
    const float* src; int base;
    if (i < 196608){ src = w0; base = 0; }
    else if (i < 262144){ src = w1 - 786432; base = WOFF_PROJ; }
    else if (i < 524288){ src = w2 - 1048576; base = WOFF_FC1; }
    else { src = w3 - 2097152; base = WOFF_FC2; }
    float4 f = *(const float4*)&src[i*4];
    union { __half h[4]; uint2 u; } pk;
    pk.h[0]=__float2half_rn(f.x); pk.h[1]=__float2half_rn(f.y);
    pk.h[2]=__float2half_rn(f.z); pk.h[3]=__float2half_rn(f.w);
    *(uint2*)&g_wall[(size_t)base + (size_t)i*4 - ((size_t)base)] = pk.u;  // base already in i*4 coords
}

// (note: mapping — i*4 spans the concatenated buffer directly since offsets
//  were chosen to match cumulative sizes: qkv 786432, proj 262144, fc1/fc2 1048576)

// ---------------- fused input-LIF + depthwise conv + residual ---------------
__global__ void __launch_bounds__(256) k_conv_lif(
        const float* __restrict__ x, const float* __restrict__ cw,
        const float* __restrict__ cb, const float* __restrict__ lifw){
    __shared__ float  xs[16*257];
    __shared__ __half sp[16*264];
    __shared__ float  ws[16*9];
    __shared__ float  wb[16];
    int tid = threadIdx.x;
    int b  = blockIdx.x >> 5;
    int c0 = (blockIdx.x & 31) * 16;
    if (tid < 16*9) ws[tid] = cw[c0*9 + tid];
    if (tid < 16)   wb[tid] = cb[c0 + tid];
    float dec = sigm(lifw[0]);
    float v[16];
    #pragma unroll
    for (int i = 0; i < 16; i++) v[i] = 0.f;
    __syncthreads();
    for (int t = 0; t < T_; t++){
        int tb = t*B_ + b;
        #pragma unroll
        for (int i = 0; i < 16; i++){
            int lin = tid + i*256;
            int cl = lin >> 8, px = lin & 255;
            float xv = x[((size_t)tb*C_ + c0 + cl)*256 + px];
            xs[cl*257 + px] = xv;
            float vv = v[i] + (xv - v[i])*dec;
            float s = (vv >= 1.0f) ? 1.f : 0.f;
            v[i] = (s > 0.f) ? 0.f : vv;
            sp[cl*264 + px] = __float2half_rn(s);
        }
        __syncthreads();
        #pragma unroll
        for (int i = 0; i < 16; i++){
            int lin = tid + i*256;
            int cl = lin & 15, n = lin >> 4;
            int hh = n >> 4, wp = n & 15;
            float acc = wb[cl];
            const float* wk = &ws[cl*9];
            #pragma unroll
            for (int kh = 0; kh < 3; kh++){
                int h2 = hh + kh - 1;
                if (h2 < 0 || h2 > 15) continue;
                #pragma unroll
                for (int kw = 0; kw < 3; kw++){
                    int w2 = wp + kw - 1;
                    if (w2 < 0 || w2 > 15) continue;
                    acc += __half2float(sp[cl*264 + h2*16 + w2]) * wk[kh*3 + kw];
                }
            }
            float val = xs[cl*257 + n] + acc;
            g_xt[((size_t)tb*256 + n)*C_ + c0 + cl] = val;
        }
        __syncthreads();
    }
}

// ---------------- LayerNorm + LIF, warp-per-token ---------------------------
__global__ void __launch_bounds__(256) k_ln_lif(
        const float* __restrict__ in, __half* __restrict__ out,
        const float* __restrict__ gam, const float* __restrict__ bet,
        const float* __restrict__ lifw, int lidx){
    int tid = threadIdx.x, wid = tid >> 5, lane = tid & 31;
    int bn = blockIdx.x*8 + wid;
    int cb = lane*16;
    float dec = sigm(lifw[lidx]);
    float gg[16], bb[16];
    #pragma unroll
    for (int i = 0; i < 4; i++){
        float4 t1 = *(const float4*)&gam[cb + i*4];
        float4 t2 = *(const float4*)&bet[cb + i*4];
        gg[i*4]=t1.x; gg[i*4+1]=t1.y; gg[i*4+2]=t1.z; gg[i*4+3]=t1.w;
        bb[i*4]=t2.x; bb[i*4+1]=t2.y; bb[i*4+2]=t2.z; bb[i*4+3]=t2.w;
    }
    float v[16];
    #pragma unroll
    for (int i = 0; i < 16; i++) v[i] = 0.f;
    for (int t = 0; t < T_; t++){
        int row = t*ROWS_PER_T + bn;
        const float* xr = in + (size_t)row*C_ + cb;
        float xv[16];
        #pragma unroll
        for (int i = 0; i < 4; i++){
            float4 x4 = *(const float4*)&xr[i*4];
            xv[i*4]=x4.x; xv[i*4+1]=x4.y; xv[i*4+2]=x4.z; xv[i*4+3]=x4.w;
        }
        float s = 0.f, ss = 0.f;
        #pragma unroll
        for (int i = 0; i < 16; i++){ s += xv[i]; ss += xv[i]*xv[i]; }
        #pragma unroll
        for (int o = 16; o > 0; o >>= 1){
            s  += __shfl_xor_sync(0xffffffffu, s,  o);
            ss += __shfl_xor_sync(0xffffffffu, ss, o);
        }
        float mean = s*(1.0f/C_);
        float var  = ss*(1.0f/C_) - mean*mean;
        float rstd = rsqrtf(var + 1e-5f);
        union { __half h[16]; uint4 u[2]; } pk;
        #pragma unroll
        for (int k = 0; k < 16; k++){
            float ln = (xv[k]-mean)*rstd*gg[k] + bb[k];
            v[k] += (ln - v[k])*dec;
            float spv = (v[k] >= 1.0f) ? 1.f : 0.f;
            pk.h[k] = __float2half_rn(spv);
            if (spv > 0.f) v[k] = 0.f;
        }
        uint4* dst = (uint4*)(out + (size_t)row*C_ + cb);
        dst[0] = pk.u[0]; dst[1] = pk.u[1];
    }
}

// ---------------- attention phase 1: kv = k^T v per (t,b,h) -----------------
__global__ void __launch_bounds__(256) k_attn_kv(){
    int blk = blockIdx.x;
    int h  = blk & (NH_-1);
    int tb = blk >> 3;
    __shared__ float ks[64*64];
    __shared__ float vs[64*64];
    int tid = threadIdx.x;
    int ti = tid >> 4, tj = tid & 15;
    float acc[4][4] = {};
    const __half* base = g_q16 + (size_t)tb*256*(3*C_);
    for (int n0 = 0; n0 < N_; n0 += 64){
        int tok = tid >> 2, doff = (tid & 3)*16;
        const __half* kr = base + (size_t)(n0+tok)*(3*C_) + C_   + h*D_ + doff;
        const __half* vr = base + (size_t)(n0+tok)*(3*C_) + 2*C_ + h*D_ + doff;
        #pragma unroll
        for (int i = 0; i < 16; i++){
            ks[tok*64 + doff + i] = __half2float(kr[i]);
            vs[tok*64 + doff + i] = __half2float(vr[i]);
        }
        __syncthreads();
        #pragma unroll 8
        for (int nn = 0; nn < 64; nn++){
            float ra[4], rb[4];
            #pragma unroll
            for (int i = 0; i < 4; i++) ra[i] = ks[nn*64 + ti*4 + i];
            #pragma unroll
            for (int j = 0; j < 4; j++) rb[j] = vs[nn*64 + tj*4 + j];
            #pragma unroll
            for (int i = 0; i < 4; i++)
                #pragma unroll
                for (int j = 0; j < 4; j++)
                    acc[i][j] += ra[i]*rb[j];
        }
        __syncthreads();
    }
    float* dst = g_kv + (size_t)blk*4096;
    #pragma unroll
    for (int i = 0; i < 4; i++)
        #pragma unroll
        for (int j = 0; j < 4; j++)
            dst[(ti*4+i)*64 + tj*4+j] = acc[i][j];
}

// ---------------- attention phase 2: a = q@kv*scale + LIF -> fp16 spikes ----
__global__ void __launch_bounds__(256) k_attn_av(const float* __restrict__ lifw){
    int blk = blockIdx.x;
    int h = blk & (NH_-1);
    int b = blk >> 3;
    __shared__ float kvs[64*64];
    int tid = threadIdx.x;
    float dec = sigm(lifw[5]);
    float v[64];
    #pragma unroll
    for (int j = 0; j < 64; j++) v[j] = 0.f;
    for (int t = 0; t < T_; t++){
        int tb = t*B_ + b;
        const float* kvsrc = g_kv + (size_t)(tb*NH_ + h)*4096;
        #pragma unroll
        for (int i = 0; i < 16; i++)
            kvs[tid + i*256] = kvsrc[tid + i*256];
        __syncthreads();
        int row = tb*256 + tid;
        const __half2* qp = (const __half2*)(g_q16 + (size_t)row*(3*C_) + h*D_);
        half2 q[32];
        #pragma unroll
        for (int i = 0; i < 32; i++) q[i] = qp[i];
        #pragma unroll
        for (int jc = 0; jc < 8; jc++){
            float s[8] = {};
            #pragma unroll 8
            for (int i2 = 0; i2 < 32; i2++){
                float2 qf = __half22float2(q[i2]);
                #pragma unroll
                for (int j = 0; j < 8; j++){
                    s[j] += qf.x*kvs[(2*i2)*64 + jc*8 + j];
                    s[j] += qf.y*kvs[(2*i2+1)*64 + jc*8 + j];
                }
            }
            union { __half hh[8]; uint4 u; } pk;
            #pragma unroll
            for (int j = 0; j < 8; j++){
                int jj = jc*8 + j;
                float a = s[j]*0.125f;
                v[jj] += (a - v[jj])*dec;
                float sp = (v[jj] >= 1.0f) ? 1.f : 0.f;
                pk.hh[j] = __float2half_rn(sp);
                if (sp > 0.f) v[jj] = 0.f;
            }
            *(uint4*)(g_a16 + (size_t)row*C_ + h*D_ + jc*8) = pk.u;
        }
        __syncthreads();
    }
}

// ---------------- host orchestration ----------------------------------------
extern "C" void kernel_launch(void* const* d_in, const int* in_sizes, int n_in,
                              void* d_out, int out_size){
    const float* x      = (const float*)d_in[0];
    const float* conv_w = (const float*)d_in[1];
    const float* conv_b = (const float*)d_in[2];
    const float* ln1_g  = (const float*)d_in[3];
    const float* ln1_b  = (const float*)d_in[4];
    const float* qkv_w  = (const float*)d_in[5];
    const float* proj_w = (const float*)d_in[6];
    const float* proj_b = (const float*)d_in[7];
    const float* ln2_g  = (const float*)d_in[8];
    const float* ln2_b  = (const float*)d_in[9];
    const float* fc1_w  = (const float*)d_in[10];
    const float* fc1_b  = (const float*)d_in[11];
    const float* fc2_w  = (const float*)d_in[12];
    const float* fc2_b  = (const float*)d_in[13];
    const float* lif_w  = (const float*)d_in[14];
    float* out = (float*)d_out;

    cudaFuncSetAttribute(tc_gemm<0>, cudaFuncAttributeMaxDynamicSharedMemorySize, GEMM_SMEM);
    cudaFuncSetAttribute(tc_gemm<1>, cudaFuncAttributeMaxDynamicSharedMemorySize, GEMM_SMEM);
    cudaFuncSetAttribute(tc_gemm<2>, cudaFuncAttributeMaxDynamicSharedMemorySize, GEMM_SMEM);
    cudaFuncSetAttribute(tc_gemm<3>, cudaFuncAttributeMaxDynamicSharedMemorySize, GEMM_SMEM);

    float *p_xt, *p_xt2;
    __half *p_h16, *p_q16, *p_a16, *p_m16, *p_w;
    cudaGetSymbolAddress((void**)&p_xt,  g_xt);
    cudaGetSymbolAddress((void**)&p_xt2, g_xt2);
    cudaGetSymbolAddress((void**)&p_h16, g_h16);
    cudaGetSymbolAddress((void**)&p_q16, g_q16);
    cudaGetSymbolAddress((void**)&p_a16, g_a16);
    cudaGetSymbolAddress((void**)&p_m16, g_m16);
    cudaGetSymbolAddress((void**)&p_w,   g_wall);

    // 1. all weight converts (one launch)
    k_f2hall<<<786432/256, 256>>>(qkv_w, proj_w, fc1_w, fc2_w);
    // 2. fused input LIF + conv + residual -> g_xt
    k_conv_lif<<<512, 256>>>(x, conv_w, conv_b, lif_w);
    // 3. LN1 + LIF -> g_h16
    k_ln_lif<<<512, 256>>>(p_xt, p_h16, ln1_g, ln1_b, lif_w, 1);
    // 4. qkv GEMM + fused qkv-LIF -> g_q16
    tc_gemm<1><<<dim3(12,128), 256, GEMM_SMEM>>>(p_h16, p_w + WOFF_QKV, nullptr, nullptr,
                                                 nullptr, p_q16, lif_w, 3*C_, C_);
    // 5. attention
    k_attn_kv<<<512, 256>>>();
    k_attn_av<<<128, 256>>>(lif_w);
    // 6. proj GEMM + bias + residual -> g_xt2
    tc_gemm<0><<<dim3(4,128), 256, GEMM_SMEM>>>(p_a16, p_w + WOFF_PROJ, proj_b, p_xt,
                                                p_xt2, nullptr, lif_w, C_, C_);
    // 7. LN2 + LIF -> g_h16
    k_ln_lif<<<512, 256>>>(p_xt2, p_h16, ln2_g, ln2_b, lif_w, 6);
    // 8. fc1 GEMM + bias + fused mlp-LIF -> g_m16
    tc_gemm<2><<<dim3(16,128), 256, GEMM_SMEM>>>(p_h16, p_w + WOFF_FC1, fc1_b, nullptr,
                                                 nullptr, p_m16, lif_w, HID_, C_);
    // 9. fc2 GEMM + bias + residual -> output (transposed, direct)
    tc_gemm<3><<<dim3(4,128), 256, GEMM_SMEM>>>(p_m16, p_w + WOFF_FC2, fc2_b, p_xt2,
                                                out, nullptr, lif_w, C_, HID_);
}